// round 13
// baseline (speedup 1.0000x reference)
#include <cuda_runtime.h>
#include <cstdint>
#include <math.h>

#define BB 8
#define NN 27380
#define PP 12000
#define POST 2000
#define NW 375            // PP/32 bit-words per row (logical)
#define NWP 384           // padded word-column count per group
#define GROUPS 375
#define PBP 2364000       // per-batch packed words: (375*384 - 375*374/2) * 32
#define NBUCK 8192

typedef unsigned int u32;
typedef unsigned long long u64;

// ---------------- scratch (device globals; zero-initialized at load) ----------------
__device__ float4 g_boxes[BB * NN];
__device__ u32    g_cnt[BB * NBUCK];       // reset by k_scan each run
__device__ u32    g_start[BB * NBUCK];
__device__ u32    g_fill[BB * NBUCK];
__device__ u64    g_keys[BB * NN];
__device__ float  g_sx1[BB * PP], g_sy1[BB * PP], g_sx2[BB * PP], g_sy2[BB * PP], g_sa[BB * PP];
// triangle-packed, group-tiled mask: word (row,w), w >= g=(row>>5), at
//   b*PBP + (C(g) + w - g)*32 + (row&31),  C(g) = g*NWP - g*(g-1)/2
__device__ u32    g_mask[BB * PBP];        // 75.6 MB -> fits L2 (126 MB)

// ---------------- kernel 1: decode boxes + bucket histogram ----------------
__global__ void k_decode(const float4* __restrict__ anchors,
                         const float4* __restrict__ deltas,
                         const float*  __restrict__ scores) {
    int i = blockIdx.x * blockDim.x + threadIdx.x;
    if (i >= BB * NN) return;
    int n = i % NN;
    float4 a = anchors[n];
    float4 d = deltas[i];

    float w  = __fadd_rn(__fsub_rn(a.z, a.x), 1.0f);
    float h  = __fadd_rn(__fsub_rn(a.w, a.y), 1.0f);
    float cx = __fadd_rn(a.x, __fmul_rn(0.5f, w));
    float cy = __fadd_rn(a.y, __fmul_rn(0.5f, h));
    float px = __fadd_rn(cx, __fmul_rn(w, d.x));
    float py = __fadd_rn(cy, __fmul_rn(h, d.y));
    float pw = __fmul_rn((float)exp((double)d.z), w);
    float ph = __fmul_rn((float)exp((double)d.w), h);
    float x1 = __fsub_rn(px, __fmul_rn(0.5f, pw));
    float y1 = __fsub_rn(py, __fmul_rn(0.5f, ph));
    float x2 = __fadd_rn(px, __fmul_rn(0.5f, __fsub_rn(pw, 2.0f)));
    float y2 = __fadd_rn(py, __fmul_rn(0.5f, __fsub_rn(ph, 2.0f)));
    g_boxes[i] = make_float4(x1, y1, x2, y2);

    float s = scores[i];
    int t = (int)(s * 8192.0f);
    if (t > NBUCK - 1) t = NBUCK - 1;
    int bi = (NBUCK - 1) - t;
    atomicAdd(&g_cnt[(i / NN) * NBUCK + bi], 1u);
}

// ---------------- kernel 2: per-batch exclusive scan (+ counter reset) ----------------
__global__ void k_scan() {
    int b = blockIdx.x, tid = threadIdx.x;
    int lane = tid & 31, wid = tid >> 5;
    __shared__ u32 wsum[32];
    int base = b * NBUCK + tid * 8;
    u32 v[8], pre[8], s = 0;
#pragma unroll
    for (int j = 0; j < 8; j++) v[j] = g_cnt[base + j];
#pragma unroll
    for (int j = 0; j < 8; j++) { pre[j] = s; s += v[j]; }
#pragma unroll
    for (int j = 0; j < 8; j++) g_cnt[base + j] = 0u;
    u32 inc = s;
#pragma unroll
    for (int o = 1; o < 32; o <<= 1) { u32 t = __shfl_up_sync(~0u, inc, o); if (lane >= o) inc += t; }
    if (lane == 31) wsum[wid] = inc;
    __syncthreads();
    if (wid == 0) {
        u32 x = wsum[lane], xin = x;
#pragma unroll
        for (int o = 1; o < 32; o <<= 1) { u32 t = __shfl_up_sync(~0u, xin, o); if (lane >= o) xin += t; }
        wsum[lane] = xin - x;
    }
    __syncthreads();
    u32 off = wsum[wid] + (inc - s);
#pragma unroll
    for (int j = 0; j < 8; j++) {
        u32 o = off + pre[j];
        g_start[base + j] = o;
        g_fill[base + j]  = o;
    }
}

// ---------------- kernel 3: scatter keys into buckets ----------------
__global__ void k_scatter(const float* __restrict__ scores) {
    int i = blockIdx.x * blockDim.x + threadIdx.x;
    if (i >= BB * NN) return;
    int b = i / NN, n = i % NN;
    float s = scores[i];
    int t = (int)(s * 8192.0f);
    if (t > NBUCK - 1) t = NBUCK - 1;
    int bi = (NBUCK - 1) - t;
    u32 pos = atomicAdd(&g_fill[b * NBUCK + bi], 1u);
    u64 key = ((u64)__float_as_uint(s) << 32) | (u64)(0xFFFFFFFFu - (u32)n);
    g_keys[(size_t)b * NN + pos] = key;
}

// ---------------- kernel 4: per-bucket insertion sort (descending) ----------------
__global__ void k_bsort() {
    int i = blockIdx.x * blockDim.x + threadIdx.x;
    if (i >= BB * NBUCK) return;
    int b = i / NBUCK, bi = i % NBUCK;
    int s = (int)g_start[b * NBUCK + bi];
    if (s >= PP) return;                       // beyond top-P: never read
    int e = (bi == NBUCK - 1) ? NN : (int)g_start[b * NBUCK + bi + 1];
    u64* keys = &g_keys[(size_t)b * NN];
    for (int p = s + 1; p < e; p++) {
        u64 k = keys[p];
        int j = p - 1;
        while (j >= s && keys[j] < k) { keys[j + 1] = keys[j]; j--; }
        keys[j + 1] = k;
    }
}

// ---------------- kernel 5: gather top-P sorted boxes (SoA) + areas ----------------
__global__ void k_gather() {
    int i = blockIdx.x * blockDim.x + threadIdx.x;
    if (i >= BB * PP) return;
    int b = i / PP, p = i % PP;
    u64 k = g_keys[(size_t)b * NN + p];
    u32 n = 0xFFFFFFFFu - (u32)(k & 0xFFFFFFFFull);
    float4 bx = g_boxes[b * NN + n];
    g_sx1[i] = bx.x; g_sy1[i] = bx.y; g_sx2[i] = bx.z; g_sy2[i] = bx.w;
    g_sa[i] = __fmul_rn(__fadd_rn(__fsub_rn(bx.z, bx.x), 1.0f),
                        __fadd_rn(__fsub_rn(bx.w, bx.y), 1.0f));
}

// exact: rn(inter/denom) > 0.7f  <=>  inter*2^25 >= 23488103*denom
__device__ __forceinline__ bool iou_exact(float inter, float denom) {
    return ((double)inter * 33554432.0) >= (23488103.0 * (double)denom);
}

// screen thresholds: CC = 7/17 (iou>0.7 <=> inter > CC*(A+B)), band +-2e-6 relative
#define THI 0.41176671f
#define TLO 0.41176271f

// ---------------- kernel 6: suppression bitmask (R5 body; packed store) ----------------
__global__ void k_mask() {
    const int b  = blockIdx.z;
    const int w0 = blockIdx.x * 32;
    const int r0 = blockIdx.y * 64;
    const int gr0 = r0 >> 5;
    if (w0 + 31 < gr0) return;                        // fully lower-triangle

    __shared__ float sx1[1024], sy1[1024], sx2p[1024], sy2p[1024], sa[1024];
    __shared__ u32 stage[2048];
    const int tid = threadIdx.x, lane = tid & 31, wi = tid >> 5;
    const int cbase = w0 * 32;
    for (int i = tid; i < 1024; i += 256) {
        int c = cbase + i;
        float x1 = 0.f, y1 = 0.f, x2 = -10.f, y2 = -10.f, a = 1.f;
        if (c < PP) {
            int g = b * PP + c;
            x1 = g_sx1[g]; y1 = g_sy1[g]; x2 = g_sx2[g]; y2 = g_sy2[g]; a = g_sa[g];
        }
        int sw = (i & 31) * 32 + (i >> 5);
        sx1[sw] = x1; sy1[sw] = y1;
        sx2p[sw] = __fadd_rn(x2, 1.0f);
        sy2p[sw] = __fadd_rn(y2, 1.0f);
        sa[sw] = a;
    }
    __syncthreads();

    const int w = w0 + lane;
    const int rbeg = r0 + wi * 8;
    float rx1[8], ry1[8], rx2p[8], ry2p[8], ra[8];
#pragma unroll
    for (int rr = 0; rr < 8; rr++) {
        int row = rbeg + rr;
        if (row < PP) {
            int g = b * PP + row;
            rx1[rr] = g_sx1[g]; ry1[rr] = g_sy1[g];
            rx2p[rr] = __fadd_rn(g_sx2[g], 1.0f);
            ry2p[rr] = __fadd_rn(g_sy2[g], 1.0f);
            ra[rr] = g_sa[g];
        } else { rx1[rr] = 0.f; ry1[rr] = 0.f; rx2p[rr] = -9.f; ry2p[rr] = -9.f; ra[rr] = 1.f; }
    }
    u32 acc[8] = {0,0,0,0,0,0,0,0};
    u32 rar[8] = {0,0,0,0,0,0,0,0};

#pragma unroll 4
    for (int t = 0; t < 32; t++) {
        int si = t * 32 + lane;
        float cx1 = sx1[si], cy1 = sy1[si], cx2p = sx2p[si], cy2p = sy2p[si], ca = sa[si];
#pragma unroll
        for (int rr = 0; rr < 8; rr++) {
            float xx1 = fmaxf(rx1[rr], cx1);
            float yy1 = fmaxf(ry1[rr], cy1);
            float ww  = __fsub_rn(fminf(rx2p[rr], cx2p), xx1);              // unclamped
            float hh  = fmaxf(__fsub_rn(fminf(ry2p[rr], cy2p), yy1), 0.0f); // one clamp
            float inter = __fmul_rn(ww, hh);
            float s     = __fadd_rn(ra[rr], ca);
            acc[rr] |= (__fmaf_rn(-THI, s, inter) > 0.0f) ? (1u << t) : 0u;
            rar[rr] |= (__fmaf_rn(-TLO, s, inter) > 0.0f) ? (1u << t) : 0u;
        }
    }
#pragma unroll
    for (int rr = 0; rr < 8; rr++) rar[rr] &= ~acc[rr];   // rare = in (TLO, THI]

    u32 any = rar[0]|rar[1]|rar[2]|rar[3]|rar[4]|rar[5]|rar[6]|rar[7];
    if (any) {
#pragma unroll
        for (int rr = 0; rr < 8; rr++) {
            u32 m = rar[rr];
            while (m) {
                int t = __ffs(m) - 1; m &= m - 1;
                int si = t * 32 + lane;
                float cx1 = sx1[si], cy1 = sy1[si], cx2p = sx2p[si], cy2p = sy2p[si], ca = sa[si];
                float xx1 = fmaxf(rx1[rr], cx1);
                float yy1 = fmaxf(ry1[rr], cy1);
                float ww  = fmaxf(__fsub_rn(fminf(rx2p[rr], cx2p), xx1), 0.0f);
                float hh  = fmaxf(__fsub_rn(fminf(ry2p[rr], cy2p), yy1), 0.0f);
                float inter = __fmul_rn(ww, hh);
                float denom = __fsub_rn(__fadd_rn(ra[rr], ca), inter);
                if (iou_exact(inter, denom)) acc[rr] |= (1u << t);
            }
        }
    }

    // stage (XOR-swizzled) then coalesced TRIANGLE-PACKED store
#pragma unroll
    for (int rr = 0; rr < 8; rr++) {
        int rl = wi * 8 + rr;
        int row = r0 + rl;
        int gi = rl >> 5, l = rl & 31;
        u32 word = acc[rr];
        if (w == (row >> 5)) word &= ~((2u << (row & 31)) - 1u);  // keep j > i
        stage[gi * 1024 + lane * 32 + ((l ^ lane) & 31)] = word;
    }
    __syncthreads();

#pragma unroll
    for (int gi = 0; gi < 2; gi++) {
        int gr = gr0 + gi;
        if (gr >= GROUPS) continue;
        int Cg = gr * NWP - (gr * (gr - 1)) / 2;      // packed base column for group gr
        size_t obase = (size_t)b * PBP;
#pragma unroll
        for (int rep = 0; rep < 4; rep++) {
            int j = rep * 256 + tid;
            int wl = j >> 5, l = j & 31;
            int wc = w0 + wl;
            if (wc < gr) continue;                    // lower triangle, never stored
            g_mask[obase + ((size_t)(Cg + wc - gr)) * 32 + l] =
                stage[gi * 1024 + wl * 32 + ((l ^ wl) & 31)];
        }
    }
}

// ---------------- kernel 7: greedy sweep + output (R5 body; packed reads) -------------
__global__ void __launch_bounds__(384, 1) k_sweep(float* __restrict__ out) {
    const int b = blockIdx.x, tid = threadIdx.x;
    const int myw = tid;
    const size_t mb = (size_t)b * PBP;
    __shared__ u32 s_diag[32];
    __shared__ int s_keep[POST];
    __shared__ u32 s_k32;
    __shared__ int s_tot;

    u32 r = 0;
    u32 cur[32], nxt[32];
    {
        const uint4* p = reinterpret_cast<const uint4*>(&g_mask[mb + (size_t)myw * 32]);  // C(0)=0
#pragma unroll
        for (int i = 0; i < 8; i++) {
            uint4 v = p[i];
            cur[4*i] = v.x; cur[4*i+1] = v.y; cur[4*i+2] = v.z; cur[4*i+3] = v.w;
        }
    }
    if (tid == 0) s_tot = 0;
    __syncthreads();

    int cb = 0;                                       // C(g)
    for (int g = 0; g < NW; g++) {
        const int cb1 = cb + (NWP - g);               // C(g+1)
        if (myw > g && g + 1 < NW) {
            const uint4* p = reinterpret_cast<const uint4*>(
                &g_mask[mb + ((size_t)(cb1 + myw - (g + 1))) * 32]);
#pragma unroll
            for (int i = 0; i < 8; i++) {
                uint4 v = p[i];
                nxt[4*i] = v.x; nxt[4*i+1] = v.y; nxt[4*i+2] = v.z; nxt[4*i+3] = v.w;
            }
        }
        if (myw == g) {
#pragma unroll
            for (int l = 0; l < 32; l++) s_diag[l] = cur[l];
            u32 rem = r;
            int cnt = s_tot;
            u32 kept = 0u;
            u32 cand = ~rem;
            while (cand && cnt < POST) {
                int l = __ffs(cand) - 1;
                kept |= 1u << l;
                s_keep[cnt++] = g * 32 + l;
                rem |= s_diag[l];
                cand &= ~rem & ~((2u << l) - 1u);
            }
            s_k32 = kept;
            s_tot = cnt;
        }
        __syncthreads();
        if (s_tot >= POST) break;
        u32 k32 = s_k32;
        if (myw > g) {
            if (k32) {
#pragma unroll
                for (int l = 0; l < 32; l++) r |= ((k32 >> l) & 1u) ? cur[l] : 0u;
            }
#pragma unroll
            for (int l = 0; l < 32; l++) cur[l] = nxt[l];
        }
        __syncthreads();
        cb = cb1;
    }

    __syncthreads();
    const int tot = s_tot;
    for (int i = tid; i < POST; i += blockDim.x) {
        float v0 = 0.f, v1 = 0.f, v2 = 0.f, v3 = 0.f, v4 = 0.f;
        if (i < tot) {
            int pos = s_keep[i];
            int gx = b * PP + pos;
            v0 = (float)b;
            v1 = g_sx1[gx]; v2 = g_sy1[gx]; v3 = g_sx2[gx]; v4 = g_sy2[gx];
        }
        float* o = out + (size_t)(b * POST + i) * 5;
        o[0] = v0; o[1] = v1; o[2] = v2; o[3] = v3; o[4] = v4;
    }
}

// ---------------- launcher ----------------
extern "C" void kernel_launch(void* const* d_in, const int* in_sizes, int n_in,
                              void* d_out, int out_size) {
    const float4* anchors = (const float4*)d_in[0];
    const float4* deltas  = (const float4*)d_in[1];
    const float*  scores  = (const float*)d_in[2];
    float* out = (float*)d_out;

    k_decode<<<(BB * NN + 255) / 256, 256>>>(anchors, deltas, scores);
    k_scan<<<BB, 1024>>>();
    k_scatter<<<(BB * NN + 255) / 256, 256>>>(scores);
    k_bsort<<<(BB * NBUCK + 255) / 256, 256>>>();
    k_gather<<<(BB * PP + 255) / 256, 256>>>();
    dim3 mg(12, 188, BB);
    k_mask<<<mg, 256>>>();
    k_sweep<<<BB, 384>>>(out);
}

// round 14
// speedup vs baseline: 1.6189x; 1.6189x over previous
#include <cuda_runtime.h>
#include <cstdint>
#include <math.h>

#define BB 8
#define NN 27380
#define PP 12000
#define POST 2000
#define NW 375            // PP/32 bit-words per row (logical)
#define NWP 384           // padded row stride in words
#define GROUPS 375
#define PB (GROUPS * NWP * 32)   // per-batch mask words (group-tiled layout)
#define NBUCK 8192

typedef unsigned int u32;
typedef unsigned long long u64;

// ---------------- scratch (device globals; zero-initialized at load) ----------------
__device__ float4 g_boxes[BB * NN];
__device__ u32    g_cnt[BB * NBUCK];       // reset by k_scan each run
__device__ u32    g_start[BB * NBUCK];
__device__ u32    g_fill[BB * NBUCK];
__device__ u64    g_keys[BB * NN];
__device__ float  g_sx1[BB * PP], g_sy1[BB * PP], g_sx2[BB * PP], g_sy2[BB * PP], g_sa[BB * PP];
// group-tiled mask: word for (row, w) at  b*PB + ((row>>5)*NWP + w)*32 + (row&31)
__device__ u32    g_mask[BB * PB];         // 147.5 MB

// ---------------- kernel 1: decode boxes + bucket histogram ----------------
__global__ void k_decode(const float4* __restrict__ anchors,
                         const float4* __restrict__ deltas,
                         const float*  __restrict__ scores) {
    int i = blockIdx.x * blockDim.x + threadIdx.x;
    if (i >= BB * NN) return;
    int n = i % NN;
    float4 a = anchors[n];
    float4 d = deltas[i];

    float w  = __fadd_rn(__fsub_rn(a.z, a.x), 1.0f);
    float h  = __fadd_rn(__fsub_rn(a.w, a.y), 1.0f);
    float cx = __fadd_rn(a.x, __fmul_rn(0.5f, w));
    float cy = __fadd_rn(a.y, __fmul_rn(0.5f, h));
    float px = __fadd_rn(cx, __fmul_rn(w, d.x));
    float py = __fadd_rn(cy, __fmul_rn(h, d.y));
    float pw = __fmul_rn((float)exp((double)d.z), w);
    float ph = __fmul_rn((float)exp((double)d.w), h);
    float x1 = __fsub_rn(px, __fmul_rn(0.5f, pw));
    float y1 = __fsub_rn(py, __fmul_rn(0.5f, ph));
    float x2 = __fadd_rn(px, __fmul_rn(0.5f, __fsub_rn(pw, 2.0f)));
    float y2 = __fadd_rn(py, __fmul_rn(0.5f, __fsub_rn(ph, 2.0f)));
    g_boxes[i] = make_float4(x1, y1, x2, y2);

    float s = scores[i];
    int t = (int)(s * 8192.0f);
    if (t > NBUCK - 1) t = NBUCK - 1;
    int bi = (NBUCK - 1) - t;
    atomicAdd(&g_cnt[(i / NN) * NBUCK + bi], 1u);
}

// ---------------- kernel 2: per-batch exclusive scan (+ counter reset) ----------------
__global__ void k_scan() {
    int b = blockIdx.x, tid = threadIdx.x;
    int lane = tid & 31, wid = tid >> 5;
    __shared__ u32 wsum[32];
    int base = b * NBUCK + tid * 8;
    u32 v[8], pre[8], s = 0;
#pragma unroll
    for (int j = 0; j < 8; j++) v[j] = g_cnt[base + j];
#pragma unroll
    for (int j = 0; j < 8; j++) { pre[j] = s; s += v[j]; }
#pragma unroll
    for (int j = 0; j < 8; j++) g_cnt[base + j] = 0u;
    u32 inc = s;
#pragma unroll
    for (int o = 1; o < 32; o <<= 1) { u32 t = __shfl_up_sync(~0u, inc, o); if (lane >= o) inc += t; }
    if (lane == 31) wsum[wid] = inc;
    __syncthreads();
    if (wid == 0) {
        u32 x = wsum[lane], xin = x;
#pragma unroll
        for (int o = 1; o < 32; o <<= 1) { u32 t = __shfl_up_sync(~0u, xin, o); if (lane >= o) xin += t; }
        wsum[lane] = xin - x;
    }
    __syncthreads();
    u32 off = wsum[wid] + (inc - s);
#pragma unroll
    for (int j = 0; j < 8; j++) {
        u32 o = off + pre[j];
        g_start[base + j] = o;
        g_fill[base + j]  = o;
    }
}

// ---------------- kernel 3: scatter keys into buckets ----------------
__global__ void k_scatter(const float* __restrict__ scores) {
    int i = blockIdx.x * blockDim.x + threadIdx.x;
    if (i >= BB * NN) return;
    int b = i / NN, n = i % NN;
    float s = scores[i];
    int t = (int)(s * 8192.0f);
    if (t > NBUCK - 1) t = NBUCK - 1;
    int bi = (NBUCK - 1) - t;
    u32 pos = atomicAdd(&g_fill[b * NBUCK + bi], 1u);
    u64 key = ((u64)__float_as_uint(s) << 32) | (u64)(0xFFFFFFFFu - (u32)n);
    g_keys[(size_t)b * NN + pos] = key;
}

// ---------------- kernel 4: per-bucket insertion sort (descending) ----------------
__global__ void k_bsort() {
    int i = blockIdx.x * blockDim.x + threadIdx.x;
    if (i >= BB * NBUCK) return;
    int b = i / NBUCK, bi = i % NBUCK;
    int s = (int)g_start[b * NBUCK + bi];
    if (s >= PP) return;                       // beyond top-P: never read
    int e = (bi == NBUCK - 1) ? NN : (int)g_start[b * NBUCK + bi + 1];
    u64* keys = &g_keys[(size_t)b * NN];
    for (int p = s + 1; p < e; p++) {
        u64 k = keys[p];
        int j = p - 1;
        while (j >= s && keys[j] < k) { keys[j + 1] = keys[j]; j--; }
        keys[j + 1] = k;
    }
}

// ---------------- kernel 5: gather top-P sorted boxes (SoA) + areas ----------------
__global__ void k_gather() {
    int i = blockIdx.x * blockDim.x + threadIdx.x;
    if (i >= BB * PP) return;
    int b = i / PP, p = i % PP;
    u64 k = g_keys[(size_t)b * NN + p];
    u32 n = 0xFFFFFFFFu - (u32)(k & 0xFFFFFFFFull);
    float4 bx = g_boxes[b * NN + n];
    g_sx1[i] = bx.x; g_sy1[i] = bx.y; g_sx2[i] = bx.z; g_sy2[i] = bx.w;
    g_sa[i] = __fmul_rn(__fadd_rn(__fsub_rn(bx.z, bx.x), 1.0f),
                        __fadd_rn(__fsub_rn(bx.w, bx.y), 1.0f));
}

// exact: rn(inter/denom) > 0.7f  <=>  inter*2^25 >= 23488103*denom
__device__ __forceinline__ bool iou_exact(float inter, float denom) {
    return ((double)inter * 33554432.0) >= (23488103.0 * (double)denom);
}

// screen thresholds: CC = 7/17 (iou>0.7 <=> inter > CC*(A+B)), band +-2e-6 relative
#define THI 0.41176671f
#define TLO 0.41176271f

// ---------------- kernel 6: suppression bitmask (R5 verbatim) ----------------
__global__ void k_mask() {
    const int b  = blockIdx.z;
    const int w0 = blockIdx.x * 32;
    const int r0 = blockIdx.y * 64;
    const int gr0 = r0 >> 5;
    if (w0 + 31 < gr0) return;                        // fully lower-triangle

    __shared__ float sx1[1024], sy1[1024], sx2p[1024], sy2p[1024], sa[1024];
    __shared__ u32 stage[2048];
    const int tid = threadIdx.x, lane = tid & 31, wi = tid >> 5;
    const int cbase = w0 * 32;
    for (int i = tid; i < 1024; i += 256) {
        int c = cbase + i;
        float x1 = 0.f, y1 = 0.f, x2 = -10.f, y2 = -10.f, a = 1.f;
        if (c < PP) {
            int g = b * PP + c;
            x1 = g_sx1[g]; y1 = g_sy1[g]; x2 = g_sx2[g]; y2 = g_sy2[g]; a = g_sa[g];
        }
        int sw = (i & 31) * 32 + (i >> 5);
        sx1[sw] = x1; sy1[sw] = y1;
        sx2p[sw] = __fadd_rn(x2, 1.0f);
        sy2p[sw] = __fadd_rn(y2, 1.0f);
        sa[sw] = a;
    }
    __syncthreads();

    const int w = w0 + lane;
    const int rbeg = r0 + wi * 8;
    float rx1[8], ry1[8], rx2p[8], ry2p[8], ra[8];
#pragma unroll
    for (int rr = 0; rr < 8; rr++) {
        int row = rbeg + rr;
        if (row < PP) {
            int g = b * PP + row;
            rx1[rr] = g_sx1[g]; ry1[rr] = g_sy1[g];
            rx2p[rr] = __fadd_rn(g_sx2[g], 1.0f);
            ry2p[rr] = __fadd_rn(g_sy2[g], 1.0f);
            ra[rr] = g_sa[g];
        } else { rx1[rr] = 0.f; ry1[rr] = 0.f; rx2p[rr] = -9.f; ry2p[rr] = -9.f; ra[rr] = 1.f; }
    }
    u32 acc[8] = {0,0,0,0,0,0,0,0};
    u32 rar[8] = {0,0,0,0,0,0,0,0};

#pragma unroll 4
    for (int t = 0; t < 32; t++) {
        int si = t * 32 + lane;
        float cx1 = sx1[si], cy1 = sy1[si], cx2p = sx2p[si], cy2p = sy2p[si], ca = sa[si];
#pragma unroll
        for (int rr = 0; rr < 8; rr++) {
            float xx1 = fmaxf(rx1[rr], cx1);
            float yy1 = fmaxf(ry1[rr], cy1);
            float ww  = __fsub_rn(fminf(rx2p[rr], cx2p), xx1);              // unclamped
            float hh  = fmaxf(__fsub_rn(fminf(ry2p[rr], cy2p), yy1), 0.0f); // one clamp
            float inter = __fmul_rn(ww, hh);
            float s     = __fadd_rn(ra[rr], ca);
            acc[rr] |= (__fmaf_rn(-THI, s, inter) > 0.0f) ? (1u << t) : 0u;
            rar[rr] |= (__fmaf_rn(-TLO, s, inter) > 0.0f) ? (1u << t) : 0u;
        }
    }
#pragma unroll
    for (int rr = 0; rr < 8; rr++) rar[rr] &= ~acc[rr];   // rare = in (TLO, THI]

    u32 any = rar[0]|rar[1]|rar[2]|rar[3]|rar[4]|rar[5]|rar[6]|rar[7];
    if (any) {
#pragma unroll
        for (int rr = 0; rr < 8; rr++) {
            u32 m = rar[rr];
            while (m) {
                int t = __ffs(m) - 1; m &= m - 1;
                int si = t * 32 + lane;
                float cx1 = sx1[si], cy1 = sy1[si], cx2p = sx2p[si], cy2p = sy2p[si], ca = sa[si];
                float xx1 = fmaxf(rx1[rr], cx1);
                float yy1 = fmaxf(ry1[rr], cy1);
                float ww  = fmaxf(__fsub_rn(fminf(rx2p[rr], cx2p), xx1), 0.0f);
                float hh  = fmaxf(__fsub_rn(fminf(ry2p[rr], cy2p), yy1), 0.0f);
                float inter = __fmul_rn(ww, hh);
                float denom = __fsub_rn(__fadd_rn(ra[rr], ca), inter);
                if (iou_exact(inter, denom)) acc[rr] |= (1u << t);
            }
        }
    }

    // stage (XOR-swizzled) then coalesced group-tiled store
#pragma unroll
    for (int rr = 0; rr < 8; rr++) {
        int rl = wi * 8 + rr;
        int row = r0 + rl;
        int gi = rl >> 5, l = rl & 31;
        u32 word = acc[rr];
        if (w == (row >> 5)) word &= ~((2u << (row & 31)) - 1u);  // keep j > i
        stage[gi * 1024 + lane * 32 + ((l ^ lane) & 31)] = word;
    }
    __syncthreads();

#pragma unroll
    for (int gi = 0; gi < 2; gi++) {
        int gr = gr0 + gi;
        if (gr >= GROUPS) continue;
        size_t obase = (size_t)b * PB + ((size_t)gr * NWP + w0) * 32;
#pragma unroll
        for (int rep = 0; rep < 4; rep++) {
            int j = rep * 256 + tid;
            int wl = j >> 5, l = j & 31;
            if (w0 + wl < gr) continue;               // lower triangle, never read
            g_mask[obase + (size_t)wl * 32 + l] = stage[gi * 1024 + wl * 32 + ((l ^ wl) & 31)];
        }
    }
}

// ---------------- kernel 7: greedy sweep + output (R5 verbatim) ----------------
__global__ void __launch_bounds__(384, 1) k_sweep(float* __restrict__ out) {
    const int b = blockIdx.x, tid = threadIdx.x;
    const int myw = tid;
    const size_t mb = (size_t)b * PB;
    __shared__ u32 s_diag[32];
    __shared__ int s_keep[POST];
    __shared__ u32 s_k32;
    __shared__ int s_tot;

    u32 r = 0;
    u32 cur[32], nxt[32];
    {
        const uint4* p = reinterpret_cast<const uint4*>(&g_mask[mb + (size_t)myw * 32]);
#pragma unroll
        for (int i = 0; i < 8; i++) {
            uint4 v = p[i];
            cur[4*i] = v.x; cur[4*i+1] = v.y; cur[4*i+2] = v.z; cur[4*i+3] = v.w;
        }
    }
    if (tid == 0) s_tot = 0;
    __syncthreads();

    for (int g = 0; g < NW; g++) {
        if (myw > g && g + 1 < NW) {
            const uint4* p = reinterpret_cast<const uint4*>(
                &g_mask[mb + ((size_t)(g + 1) * NWP + myw) * 32]);
#pragma unroll
            for (int i = 0; i < 8; i++) {
                uint4 v = p[i];
                nxt[4*i] = v.x; nxt[4*i+1] = v.y; nxt[4*i+2] = v.z; nxt[4*i+3] = v.w;
            }
        }
        if (myw == g) {
#pragma unroll
            for (int l = 0; l < 32; l++) s_diag[l] = cur[l];
            u32 rem = r;
            int cnt = s_tot;
            u32 kept = 0u;
            u32 cand = ~rem;
            while (cand && cnt < POST) {
                int l = __ffs(cand) - 1;
                kept |= 1u << l;
                s_keep[cnt++] = g * 32 + l;
                rem |= s_diag[l];
                cand &= ~rem & ~((2u << l) - 1u);
            }
            s_k32 = kept;
            s_tot = cnt;
        }
        __syncthreads();
        if (s_tot >= POST) break;
        u32 k32 = s_k32;
        if (myw > g) {
            if (k32) {
#pragma unroll
                for (int l = 0; l < 32; l++) r |= ((k32 >> l) & 1u) ? cur[l] : 0u;
            }
#pragma unroll
            for (int l = 0; l < 32; l++) cur[l] = nxt[l];
        }
        __syncthreads();
    }

    __syncthreads();
    const int tot = s_tot;
    for (int i = tid; i < POST; i += blockDim.x) {
        float v0 = 0.f, v1 = 0.f, v2 = 0.f, v3 = 0.f, v4 = 0.f;
        if (i < tot) {
            int pos = s_keep[i];
            int gx = b * PP + pos;
            v0 = (float)b;
            v1 = g_sx1[gx]; v2 = g_sy1[gx]; v3 = g_sx2[gx]; v4 = g_sy2[gx];
        }
        float* o = out + (size_t)(b * POST + i) * 5;
        o[0] = v0; o[1] = v1; o[2] = v2; o[3] = v3; o[4] = v4;
    }
}

// ---------------- launcher ----------------
extern "C" void kernel_launch(void* const* d_in, const int* in_sizes, int n_in,
                              void* d_out, int out_size) {
    const float4* anchors = (const float4*)d_in[0];
    const float4* deltas  = (const float4*)d_in[1];
    const float*  scores  = (const float*)d_in[2];
    float* out = (float*)d_out;

    k_decode<<<(BB * NN + 255) / 256, 256>>>(anchors, deltas, scores);
    k_scan<<<BB, 1024>>>();
    k_scatter<<<(BB * NN + 255) / 256, 256>>>(scores);
    k_bsort<<<(BB * NBUCK + 255) / 256, 256>>>();
    k_gather<<<(BB * PP + 255) / 256, 256>>>();
    dim3 mg(12, 188, BB);
    k_mask<<<mg, 256>>>();
    k_sweep<<<BB, 384>>>(out);
}

// round 15
// speedup vs baseline: 3.4410x; 2.1255x over previous
#include <cuda_runtime.h>
#include <cstdint>
#include <math.h>

#define BB 8
#define NN 27380
#define PP 12000
#define POST 2000
#define NW 375            // PP/32 bit-words per row (logical)
#define NWP 384           // padded row stride in words
#define GROUPS 375
#define PB (GROUPS * NWP * 32)   // per-batch mask words (group-tiled layout)
#define NBUCK 8192
#define W1 192            // phase-0 column-word / group limit (rows/cols < 6144)
#define RB1 96            // row blocks (64 rows) covering rows < 6144
#define WB1 6             // col blocks (32 words) covering words < 192

typedef unsigned int u32;
typedef unsigned long long u64;

// ---------------- scratch (device globals; zero-initialized at load) ----------------
__device__ float4 g_boxes[BB * NN];
__device__ u32    g_cnt[BB * NBUCK];       // reset by k_scan each run
__device__ u32    g_start[BB * NBUCK];
__device__ u32    g_fill[BB * NBUCK];
__device__ u64    g_keys[BB * NN];
__device__ float  g_sx1[BB * PP], g_sy1[BB * PP], g_sx2[BB * PP], g_sy2[BB * PP], g_sa[BB * PP];
__device__ u32    g_mask[BB * PB];         // 147.5 MB
// sweep phase-0 -> phase-1 handoff state (deterministic data flow)
__device__ u32    g_rsave[BB][384];
__device__ int    g_keepG[BB][POST];
__device__ int    g_totG[BB];
__device__ int    g_doneG[BB];

// ---------------- kernel 1: decode boxes + bucket histogram ----------------
__global__ void k_decode(const float4* __restrict__ anchors,
                         const float4* __restrict__ deltas,
                         const float*  __restrict__ scores) {
    int i = blockIdx.x * blockDim.x + threadIdx.x;
    if (i < BB) g_doneG[i] = 0;            // reset per replay (runs before sweeps)
    if (i >= BB * NN) return;
    int n = i % NN;
    float4 a = anchors[n];
    float4 d = deltas[i];

    float w  = __fadd_rn(__fsub_rn(a.z, a.x), 1.0f);
    float h  = __fadd_rn(__fsub_rn(a.w, a.y), 1.0f);
    float cx = __fadd_rn(a.x, __fmul_rn(0.5f, w));
    float cy = __fadd_rn(a.y, __fmul_rn(0.5f, h));
    float px = __fadd_rn(cx, __fmul_rn(w, d.x));
    float py = __fadd_rn(cy, __fmul_rn(h, d.y));
    float pw = __fmul_rn((float)exp((double)d.z), w);
    float ph = __fmul_rn((float)exp((double)d.w), h);
    float x1 = __fsub_rn(px, __fmul_rn(0.5f, pw));
    float y1 = __fsub_rn(py, __fmul_rn(0.5f, ph));
    float x2 = __fadd_rn(px, __fmul_rn(0.5f, __fsub_rn(pw, 2.0f)));
    float y2 = __fadd_rn(py, __fmul_rn(0.5f, __fsub_rn(ph, 2.0f)));
    g_boxes[i] = make_float4(x1, y1, x2, y2);

    float s = scores[i];
    int t = (int)(s * 8192.0f);
    if (t > NBUCK - 1) t = NBUCK - 1;
    int bi = (NBUCK - 1) - t;
    atomicAdd(&g_cnt[(i / NN) * NBUCK + bi], 1u);
}

// ---------------- kernel 2: per-batch exclusive scan (+ counter reset) ----------------
__global__ void k_scan() {
    int b = blockIdx.x, tid = threadIdx.x;
    int lane = tid & 31, wid = tid >> 5;
    __shared__ u32 wsum[32];
    int base = b * NBUCK + tid * 8;
    u32 v[8], pre[8], s = 0;
#pragma unroll
    for (int j = 0; j < 8; j++) v[j] = g_cnt[base + j];
#pragma unroll
    for (int j = 0; j < 8; j++) { pre[j] = s; s += v[j]; }
#pragma unroll
    for (int j = 0; j < 8; j++) g_cnt[base + j] = 0u;
    u32 inc = s;
#pragma unroll
    for (int o = 1; o < 32; o <<= 1) { u32 t = __shfl_up_sync(~0u, inc, o); if (lane >= o) inc += t; }
    if (lane == 31) wsum[wid] = inc;
    __syncthreads();
    if (wid == 0) {
        u32 x = wsum[lane], xin = x;
#pragma unroll
        for (int o = 1; o < 32; o <<= 1) { u32 t = __shfl_up_sync(~0u, xin, o); if (lane >= o) xin += t; }
        wsum[lane] = xin - x;
    }
    __syncthreads();
    u32 off = wsum[wid] + (inc - s);
#pragma unroll
    for (int j = 0; j < 8; j++) {
        u32 o = off + pre[j];
        g_start[base + j] = o;
        g_fill[base + j]  = o;
    }
}

// ---------------- kernel 3: scatter keys into buckets ----------------
__global__ void k_scatter(const float* __restrict__ scores) {
    int i = blockIdx.x * blockDim.x + threadIdx.x;
    if (i >= BB * NN) return;
    int b = i / NN, n = i % NN;
    float s = scores[i];
    int t = (int)(s * 8192.0f);
    if (t > NBUCK - 1) t = NBUCK - 1;
    int bi = (NBUCK - 1) - t;
    u32 pos = atomicAdd(&g_fill[b * NBUCK + bi], 1u);
    u64 key = ((u64)__float_as_uint(s) << 32) | (u64)(0xFFFFFFFFu - (u32)n);
    g_keys[(size_t)b * NN + pos] = key;
}

// ---------------- kernel 4: per-bucket insertion sort (descending) ----------------
__global__ void k_bsort() {
    int i = blockIdx.x * blockDim.x + threadIdx.x;
    if (i >= BB * NBUCK) return;
    int b = i / NBUCK, bi = i % NBUCK;
    int s = (int)g_start[b * NBUCK + bi];
    if (s >= PP) return;                       // beyond top-P: never read
    int e = (bi == NBUCK - 1) ? NN : (int)g_start[b * NBUCK + bi + 1];
    u64* keys = &g_keys[(size_t)b * NN];
    for (int p = s + 1; p < e; p++) {
        u64 k = keys[p];
        int j = p - 1;
        while (j >= s && keys[j] < k) { keys[j + 1] = keys[j]; j--; }
        keys[j + 1] = k;
    }
}

// ---------------- kernel 5: gather top-P sorted boxes (SoA) + areas ----------------
__global__ void k_gather() {
    int i = blockIdx.x * blockDim.x + threadIdx.x;
    if (i >= BB * PP) return;
    int b = i / PP, p = i % PP;
    u64 k = g_keys[(size_t)b * NN + p];
    u32 n = 0xFFFFFFFFu - (u32)(k & 0xFFFFFFFFull);
    float4 bx = g_boxes[b * NN + n];
    g_sx1[i] = bx.x; g_sy1[i] = bx.y; g_sx2[i] = bx.z; g_sy2[i] = bx.w;
    g_sa[i] = __fmul_rn(__fadd_rn(__fsub_rn(bx.z, bx.x), 1.0f),
                        __fadd_rn(__fsub_rn(bx.w, bx.y), 1.0f));
}

// exact: rn(inter/denom) > 0.7f  <=>  inter*2^25 >= 23488103*denom
__device__ __forceinline__ bool iou_exact(float inter, float denom) {
    return ((double)inter * 33554432.0) >= (23488103.0 * (double)denom);
}

// screen thresholds: CC = 7/17 (iou>0.7 <=> inter > CC*(A+B)), band +-2e-6 relative
#define THI 0.41176671f
#define TLO 0.41176271f

// ---------------- mask body (R5 verbatim, parameterized) ----------------
__device__ __forceinline__ void mask_body(int b, int w0, int r0) {
    const int gr0 = r0 >> 5;
    if (w0 + 31 < gr0) return;                        // fully lower-triangle

    __shared__ float sx1[1024], sy1[1024], sx2p[1024], sy2p[1024], sa[1024];
    __shared__ u32 stage[2048];
    const int tid = threadIdx.x, lane = tid & 31, wi = tid >> 5;
    const int cbase = w0 * 32;
    for (int i = tid; i < 1024; i += 256) {
        int c = cbase + i;
        float x1 = 0.f, y1 = 0.f, x2 = -10.f, y2 = -10.f, a = 1.f;
        if (c < PP) {
            int g = b * PP + c;
            x1 = g_sx1[g]; y1 = g_sy1[g]; x2 = g_sx2[g]; y2 = g_sy2[g]; a = g_sa[g];
        }
        int sw = (i & 31) * 32 + (i >> 5);
        sx1[sw] = x1; sy1[sw] = y1;
        sx2p[sw] = __fadd_rn(x2, 1.0f);
        sy2p[sw] = __fadd_rn(y2, 1.0f);
        sa[sw] = a;
    }
    __syncthreads();

    const int w = w0 + lane;
    const int rbeg = r0 + wi * 8;
    float rx1[8], ry1[8], rx2p[8], ry2p[8], ra[8];
#pragma unroll
    for (int rr = 0; rr < 8; rr++) {
        int row = rbeg + rr;
        if (row < PP) {
            int g = b * PP + row;
            rx1[rr] = g_sx1[g]; ry1[rr] = g_sy1[g];
            rx2p[rr] = __fadd_rn(g_sx2[g], 1.0f);
            ry2p[rr] = __fadd_rn(g_sy2[g], 1.0f);
            ra[rr] = g_sa[g];
        } else { rx1[rr] = 0.f; ry1[rr] = 0.f; rx2p[rr] = -9.f; ry2p[rr] = -9.f; ra[rr] = 1.f; }
    }
    u32 acc[8] = {0,0,0,0,0,0,0,0};
    u32 rar[8] = {0,0,0,0,0,0,0,0};

#pragma unroll 4
    for (int t = 0; t < 32; t++) {
        int si = t * 32 + lane;
        float cx1 = sx1[si], cy1 = sy1[si], cx2p = sx2p[si], cy2p = sy2p[si], ca = sa[si];
#pragma unroll
        for (int rr = 0; rr < 8; rr++) {
            float xx1 = fmaxf(rx1[rr], cx1);
            float yy1 = fmaxf(ry1[rr], cy1);
            float ww  = __fsub_rn(fminf(rx2p[rr], cx2p), xx1);
            float hh  = fmaxf(__fsub_rn(fminf(ry2p[rr], cy2p), yy1), 0.0f);
            float inter = __fmul_rn(ww, hh);
            float s     = __fadd_rn(ra[rr], ca);
            acc[rr] |= (__fmaf_rn(-THI, s, inter) > 0.0f) ? (1u << t) : 0u;
            rar[rr] |= (__fmaf_rn(-TLO, s, inter) > 0.0f) ? (1u << t) : 0u;
        }
    }
#pragma unroll
    for (int rr = 0; rr < 8; rr++) rar[rr] &= ~acc[rr];

    u32 any = rar[0]|rar[1]|rar[2]|rar[3]|rar[4]|rar[5]|rar[6]|rar[7];
    if (any) {
#pragma unroll
        for (int rr = 0; rr < 8; rr++) {
            u32 m = rar[rr];
            while (m) {
                int t = __ffs(m) - 1; m &= m - 1;
                int si = t * 32 + lane;
                float cx1 = sx1[si], cy1 = sy1[si], cx2p = sx2p[si], cy2p = sy2p[si], ca = sa[si];
                float xx1 = fmaxf(rx1[rr], cx1);
                float yy1 = fmaxf(ry1[rr], cy1);
                float ww  = fmaxf(__fsub_rn(fminf(rx2p[rr], cx2p), xx1), 0.0f);
                float hh  = fmaxf(__fsub_rn(fminf(ry2p[rr], cy2p), yy1), 0.0f);
                float inter = __fmul_rn(ww, hh);
                float denom = __fsub_rn(__fadd_rn(ra[rr], ca), inter);
                if (iou_exact(inter, denom)) acc[rr] |= (1u << t);
            }
        }
    }

#pragma unroll
    for (int rr = 0; rr < 8; rr++) {
        int rl = wi * 8 + rr;
        int row = r0 + rl;
        int gi = rl >> 5, l = rl & 31;
        u32 word = acc[rr];
        if (w == (row >> 5)) word &= ~((2u << (row & 31)) - 1u);
        stage[gi * 1024 + lane * 32 + ((l ^ lane) & 31)] = word;
    }
    __syncthreads();

#pragma unroll
    for (int gi = 0; gi < 2; gi++) {
        int gr = gr0 + gi;
        if (gr >= GROUPS) continue;
        size_t obase = (size_t)b * PB + ((size_t)gr * NWP + w0) * 32;
#pragma unroll
        for (int rep = 0; rep < 4; rep++) {
            int j = rep * 256 + tid;
            int wl = j >> 5, l = j & 31;
            if (w0 + wl < gr) continue;
            g_mask[obase + (size_t)wl * 32 + l] = stage[gi * 1024 + wl * 32 + ((l ^ wl) & 31)];
        }
    }
}

// mask phase 1: corner (rows<6144 x words<192) — launched with grid (WB1, RB1, BB)
__global__ void k_mask() { mask_body(blockIdx.z, blockIdx.x * 32, blockIdx.y * 64); }

// mask phase 2: everything else; skipped entirely when the phase-0 sweep finished
__global__ void k_mask2() {
    int b = blockIdx.z;
    if (g_doneG[b]) return;
    if (blockIdx.x < WB1 && blockIdx.y < RB1) return;   // fully inside corner
    mask_body(b, blockIdx.x * 32, blockIdx.y * 64);
}

// ---------------- greedy sweep (R5 body + phase-0/1 state handoff) ----------------
__global__ void __launch_bounds__(384, 1) k_sweep(float* __restrict__ out, int phase) {
    const int b = blockIdx.x, tid = threadIdx.x;
    const int myw = tid;
    const size_t mb = (size_t)b * PB;
    __shared__ u32 s_diag[32];
    __shared__ int s_keep[POST];
    __shared__ u32 s_k32;
    __shared__ int s_tot;

    if (phase == 1 && g_doneG[b]) return;

    const int gStart = phase ? W1 : 0;
    const int gEnd   = phase ? NW : W1;
    const int lim    = phase ? NW : W1;

    u32 r = 0;
    if (phase == 1) {
        int T = g_totG[b];
        for (int i = tid; i < T; i += 384) s_keep[i] = g_keepG[b][i];
        if (tid == 0) s_tot = T;
        __syncthreads();
        if (myw < W1) {
            r = g_rsave[b][myw];
        } else if (myw < NW) {
            // recover removed-bits for columns >= W1 by ORing all kept rows
            for (int j = 0; j < T; j += 8) {
                u32 m[8];
#pragma unroll
                for (int q = 0; q < 8; q++) {
                    int idx = j + q; idx = idx < T ? idx : T - 1;
                    int row = s_keep[idx];
                    m[q] = g_mask[mb + ((size_t)(row >> 5) * NWP + myw) * 32 + (row & 31)];
                }
#pragma unroll
                for (int q = 0; q < 8; q++) r |= m[q];
            }
        }
    } else {
        if (tid == 0) s_tot = 0;
    }

    u32 cur[32], nxt[32];
    if (myw >= gStart && myw < lim) {
        const uint4* p = reinterpret_cast<const uint4*>(
            &g_mask[mb + ((size_t)gStart * NWP + myw) * 32]);
#pragma unroll
        for (int i = 0; i < 8; i++) {
            uint4 v = p[i];
            cur[4*i] = v.x; cur[4*i+1] = v.y; cur[4*i+2] = v.z; cur[4*i+3] = v.w;
        }
    }
    __syncthreads();

    for (int g = gStart; g < gEnd; g++) {
        if (myw > g && myw < lim && g + 1 < gEnd) {
            const uint4* p = reinterpret_cast<const uint4*>(
                &g_mask[mb + ((size_t)(g + 1) * NWP + myw) * 32]);
#pragma unroll
            for (int i = 0; i < 8; i++) {
                uint4 v = p[i];
                nxt[4*i] = v.x; nxt[4*i+1] = v.y; nxt[4*i+2] = v.z; nxt[4*i+3] = v.w;
            }
        }
        if (myw == g) {
#pragma unroll
            for (int l = 0; l < 32; l++) s_diag[l] = cur[l];
            u32 rem = r;
            int cnt = s_tot;
            u32 kept = 0u;
            u32 cand = ~rem;
            while (cand && cnt < POST) {
                int l = __ffs(cand) - 1;
                kept |= 1u << l;
                s_keep[cnt++] = g * 32 + l;
                rem |= s_diag[l];
                cand &= ~rem & ~((2u << l) - 1u);
            }
            s_k32 = kept;
            s_tot = cnt;
        }
        __syncthreads();
        if (s_tot >= POST) break;
        u32 k32 = s_k32;
        if (myw > g && myw < lim) {
            if (k32) {
#pragma unroll
                for (int l = 0; l < 32; l++) r |= ((k32 >> l) & 1u) ? cur[l] : 0u;
            }
#pragma unroll
            for (int l = 0; l < 32; l++) cur[l] = nxt[l];
        }
        __syncthreads();
    }

    __syncthreads();
    const int tot = s_tot;

    if (phase == 0) {
        g_rsave[b][myw] = r;
        for (int i = tid; i < tot; i += 384) g_keepG[b][i] = s_keep[i];
        if (tid == 0) { g_totG[b] = tot; g_doneG[b] = (tot >= POST) ? 1 : 0; }
        if (tot < POST) return;                 // phase 1 finishes & writes output
    }

    for (int i = tid; i < POST; i += blockDim.x) {
        float v0 = 0.f, v1 = 0.f, v2 = 0.f, v3 = 0.f, v4 = 0.f;
        if (i < tot) {
            int pos = s_keep[i];
            int gx = b * PP + pos;
            v0 = (float)b;
            v1 = g_sx1[gx]; v2 = g_sy1[gx]; v3 = g_sx2[gx]; v4 = g_sy2[gx];
        }
        float* o = out + (size_t)(b * POST + i) * 5;
        o[0] = v0; o[1] = v1; o[2] = v2; o[3] = v3; o[4] = v4;
    }
}

// ---------------- launcher ----------------
extern "C" void kernel_launch(void* const* d_in, const int* in_sizes, int n_in,
                              void* d_out, int out_size) {
    const float4* anchors = (const float4*)d_in[0];
    const float4* deltas  = (const float4*)d_in[1];
    const float*  scores  = (const float*)d_in[2];
    float* out = (float*)d_out;

    k_decode<<<(BB * NN + 255) / 256, 256>>>(anchors, deltas, scores);
    k_scan<<<BB, 1024>>>();
    k_scatter<<<(BB * NN + 255) / 256, 256>>>(scores);
    k_bsort<<<(BB * NBUCK + 255) / 256, 256>>>();
    k_gather<<<(BB * PP + 255) / 256, 256>>>();
    dim3 m1(WB1, RB1, BB);
    k_mask<<<m1, 256>>>();                     // corner only
    k_sweep<<<BB, 384>>>(out, 0);              // phase 0 (192 groups)
    dim3 m2(12, 188, BB);
    k_mask2<<<m2, 256>>>();                    // rest (skips when done)
    k_sweep<<<BB, 384>>>(out, 1);              // resume (skips when done)
}

// round 16
// speedup vs baseline: 3.9743x; 1.1550x over previous
#include <cuda_runtime.h>
#include <cstdint>
#include <math.h>

#define BB 8
#define NN 27380
#define PP 12000
#define POST 2000
#define NW 375            // PP/32 bit-words per row (logical)
#define NWP 384           // padded row stride in words
#define GROUPS 375
#define PB (GROUPS * NWP * 32)   // per-batch mask words (group-tiled layout)
#define NBUCK 8192
#define W1 160            // phase-0 column-word / group limit (rows/cols < 5120)
#define RB1 80            // row blocks (64 rows) covering rows < 5120
#define WB1 5             // col blocks (32 words) covering words < 160

typedef unsigned int u32;
typedef unsigned long long u64;

// ---------------- scratch (device globals; zero-initialized at load) ----------------
__device__ float4 g_boxes[BB * NN];
__device__ u32    g_cnt[BB * NBUCK];       // reset by k_scan each run
__device__ u32    g_start[BB * NBUCK];
__device__ u32    g_fill[BB * NBUCK];
__device__ u64    g_keys[BB * NN];
__device__ float  g_sx1[BB * PP], g_sy1[BB * PP], g_sx2[BB * PP], g_sy2[BB * PP], g_sa[BB * PP];
__device__ u32    g_mask[BB * PB];         // 147.5 MB
// sweep phase-0 -> phase-1 handoff state (deterministic data flow)
__device__ u32    g_rsave[BB][384];
__device__ int    g_keepG[BB][POST];
__device__ int    g_totG[BB];
__device__ int    g_doneG[BB];

// ---------------- kernel 1: decode boxes + bucket histogram ----------------
__global__ void k_decode(const float4* __restrict__ anchors,
                         const float4* __restrict__ deltas,
                         const float*  __restrict__ scores) {
    int i = blockIdx.x * blockDim.x + threadIdx.x;
    if (i < BB) g_doneG[i] = 0;            // reset per replay (runs before sweeps)
    if (i >= BB * NN) return;
    int n = i % NN;
    float4 a = anchors[n];
    float4 d = deltas[i];

    float w  = __fadd_rn(__fsub_rn(a.z, a.x), 1.0f);
    float h  = __fadd_rn(__fsub_rn(a.w, a.y), 1.0f);
    float cx = __fadd_rn(a.x, __fmul_rn(0.5f, w));
    float cy = __fadd_rn(a.y, __fmul_rn(0.5f, h));
    float px = __fadd_rn(cx, __fmul_rn(w, d.x));
    float py = __fadd_rn(cy, __fmul_rn(h, d.y));
    float pw = __fmul_rn((float)exp((double)d.z), w);
    float ph = __fmul_rn((float)exp((double)d.w), h);
    float x1 = __fsub_rn(px, __fmul_rn(0.5f, pw));
    float y1 = __fsub_rn(py, __fmul_rn(0.5f, ph));
    float x2 = __fadd_rn(px, __fmul_rn(0.5f, __fsub_rn(pw, 2.0f)));
    float y2 = __fadd_rn(py, __fmul_rn(0.5f, __fsub_rn(ph, 2.0f)));
    g_boxes[i] = make_float4(x1, y1, x2, y2);

    float s = scores[i];
    int t = (int)(s * 8192.0f);
    if (t > NBUCK - 1) t = NBUCK - 1;
    int bi = (NBUCK - 1) - t;
    atomicAdd(&g_cnt[(i / NN) * NBUCK + bi], 1u);
}

// ---------------- kernel 2: per-batch exclusive scan (+ counter reset) ----------------
__global__ void k_scan() {
    int b = blockIdx.x, tid = threadIdx.x;
    int lane = tid & 31, wid = tid >> 5;
    __shared__ u32 wsum[32];
    int base = b * NBUCK + tid * 8;
    u32 v[8], pre[8], s = 0;
#pragma unroll
    for (int j = 0; j < 8; j++) v[j] = g_cnt[base + j];
#pragma unroll
    for (int j = 0; j < 8; j++) { pre[j] = s; s += v[j]; }
#pragma unroll
    for (int j = 0; j < 8; j++) g_cnt[base + j] = 0u;
    u32 inc = s;
#pragma unroll
    for (int o = 1; o < 32; o <<= 1) { u32 t = __shfl_up_sync(~0u, inc, o); if (lane >= o) inc += t; }
    if (lane == 31) wsum[wid] = inc;
    __syncthreads();
    if (wid == 0) {
        u32 x = wsum[lane], xin = x;
#pragma unroll
        for (int o = 1; o < 32; o <<= 1) { u32 t = __shfl_up_sync(~0u, xin, o); if (lane >= o) xin += t; }
        wsum[lane] = xin - x;
    }
    __syncthreads();
    u32 off = wsum[wid] + (inc - s);
#pragma unroll
    for (int j = 0; j < 8; j++) {
        u32 o = off + pre[j];
        g_start[base + j] = o;
        g_fill[base + j]  = o;
    }
}

// ---------------- kernel 3: scatter keys into buckets ----------------
__global__ void k_scatter(const float* __restrict__ scores) {
    int i = blockIdx.x * blockDim.x + threadIdx.x;
    if (i >= BB * NN) return;
    int b = i / NN, n = i % NN;
    float s = scores[i];
    int t = (int)(s * 8192.0f);
    if (t > NBUCK - 1) t = NBUCK - 1;
    int bi = (NBUCK - 1) - t;
    u32 pos = atomicAdd(&g_fill[b * NBUCK + bi], 1u);
    u64 key = ((u64)__float_as_uint(s) << 32) | (u64)(0xFFFFFFFFu - (u32)n);
    g_keys[(size_t)b * NN + pos] = key;
}

// ---------------- kernel 4: per-bucket insertion sort (descending) ----------------
__global__ void k_bsort() {
    int i = blockIdx.x * blockDim.x + threadIdx.x;
    if (i >= BB * NBUCK) return;
    int b = i / NBUCK, bi = i % NBUCK;
    int s = (int)g_start[b * NBUCK + bi];
    if (s >= PP) return;                       // beyond top-P: never read
    int e = (bi == NBUCK - 1) ? NN : (int)g_start[b * NBUCK + bi + 1];
    u64* keys = &g_keys[(size_t)b * NN];
    for (int p = s + 1; p < e; p++) {
        u64 k = keys[p];
        int j = p - 1;
        while (j >= s && keys[j] < k) { keys[j + 1] = keys[j]; j--; }
        keys[j + 1] = k;
    }
}

// ---------------- kernel 5: gather top-P sorted boxes (SoA) + areas ----------------
__global__ void k_gather() {
    int i = blockIdx.x * blockDim.x + threadIdx.x;
    if (i >= BB * PP) return;
    int b = i / PP, p = i % PP;
    u64 k = g_keys[(size_t)b * NN + p];
    u32 n = 0xFFFFFFFFu - (u32)(k & 0xFFFFFFFFull);
    float4 bx = g_boxes[b * NN + n];
    g_sx1[i] = bx.x; g_sy1[i] = bx.y; g_sx2[i] = bx.z; g_sy2[i] = bx.w;
    g_sa[i] = __fmul_rn(__fadd_rn(__fsub_rn(bx.z, bx.x), 1.0f),
                        __fadd_rn(__fsub_rn(bx.w, bx.y), 1.0f));
}

// exact: rn(inter/denom) > 0.7f  <=>  inter*2^25 >= 23488103*denom
__device__ __forceinline__ bool iou_exact(float inter, float denom) {
    return ((double)inter * 33554432.0) >= (23488103.0 * (double)denom);
}

// screen thresholds: CC = 7/17 (iou>0.7 <=> inter > CC*(A+B)), band +-2e-6 relative
#define THI 0.41176671f
#define TLO 0.41176271f

// ---------------- mask body (R5 verbatim, parameterized) ----------------
__device__ __forceinline__ void mask_body(int b, int w0, int r0) {
    const int gr0 = r0 >> 5;
    if (w0 + 31 < gr0) return;                        // fully lower-triangle

    __shared__ float sx1[1024], sy1[1024], sx2p[1024], sy2p[1024], sa[1024];
    __shared__ u32 stage[2048];
    const int tid = threadIdx.x, lane = tid & 31, wi = tid >> 5;
    const int cbase = w0 * 32;
    for (int i = tid; i < 1024; i += 256) {
        int c = cbase + i;
        float x1 = 0.f, y1 = 0.f, x2 = -10.f, y2 = -10.f, a = 1.f;
        if (c < PP) {
            int g = b * PP + c;
            x1 = g_sx1[g]; y1 = g_sy1[g]; x2 = g_sx2[g]; y2 = g_sy2[g]; a = g_sa[g];
        }
        int sw = (i & 31) * 32 + (i >> 5);
        sx1[sw] = x1; sy1[sw] = y1;
        sx2p[sw] = __fadd_rn(x2, 1.0f);
        sy2p[sw] = __fadd_rn(y2, 1.0f);
        sa[sw] = a;
    }
    __syncthreads();

    const int w = w0 + lane;
    const int rbeg = r0 + wi * 8;
    float rx1[8], ry1[8], rx2p[8], ry2p[8], ra[8];
#pragma unroll
    for (int rr = 0; rr < 8; rr++) {
        int row = rbeg + rr;
        if (row < PP) {
            int g = b * PP + row;
            rx1[rr] = g_sx1[g]; ry1[rr] = g_sy1[g];
            rx2p[rr] = __fadd_rn(g_sx2[g], 1.0f);
            ry2p[rr] = __fadd_rn(g_sy2[g], 1.0f);
            ra[rr] = g_sa[g];
        } else { rx1[rr] = 0.f; ry1[rr] = 0.f; rx2p[rr] = -9.f; ry2p[rr] = -9.f; ra[rr] = 1.f; }
    }
    u32 acc[8] = {0,0,0,0,0,0,0,0};
    u32 rar[8] = {0,0,0,0,0,0,0,0};

#pragma unroll 4
    for (int t = 0; t < 32; t++) {
        int si = t * 32 + lane;
        float cx1 = sx1[si], cy1 = sy1[si], cx2p = sx2p[si], cy2p = sy2p[si], ca = sa[si];
#pragma unroll
        for (int rr = 0; rr < 8; rr++) {
            float xx1 = fmaxf(rx1[rr], cx1);
            float yy1 = fmaxf(ry1[rr], cy1);
            float ww  = __fsub_rn(fminf(rx2p[rr], cx2p), xx1);
            float hh  = fmaxf(__fsub_rn(fminf(ry2p[rr], cy2p), yy1), 0.0f);
            float inter = __fmul_rn(ww, hh);
            float s     = __fadd_rn(ra[rr], ca);
            acc[rr] |= (__fmaf_rn(-THI, s, inter) > 0.0f) ? (1u << t) : 0u;
            rar[rr] |= (__fmaf_rn(-TLO, s, inter) > 0.0f) ? (1u << t) : 0u;
        }
    }
#pragma unroll
    for (int rr = 0; rr < 8; rr++) rar[rr] &= ~acc[rr];

    u32 any = rar[0]|rar[1]|rar[2]|rar[3]|rar[4]|rar[5]|rar[6]|rar[7];
    if (any) {
#pragma unroll
        for (int rr = 0; rr < 8; rr++) {
            u32 m = rar[rr];
            while (m) {
                int t = __ffs(m) - 1; m &= m - 1;
                int si = t * 32 + lane;
                float cx1 = sx1[si], cy1 = sy1[si], cx2p = sx2p[si], cy2p = sy2p[si], ca = sa[si];
                float xx1 = fmaxf(rx1[rr], cx1);
                float yy1 = fmaxf(ry1[rr], cy1);
                float ww  = fmaxf(__fsub_rn(fminf(rx2p[rr], cx2p), xx1), 0.0f);
                float hh  = fmaxf(__fsub_rn(fminf(ry2p[rr], cy2p), yy1), 0.0f);
                float inter = __fmul_rn(ww, hh);
                float denom = __fsub_rn(__fadd_rn(ra[rr], ca), inter);
                if (iou_exact(inter, denom)) acc[rr] |= (1u << t);
            }
        }
    }

#pragma unroll
    for (int rr = 0; rr < 8; rr++) {
        int rl = wi * 8 + rr;
        int row = r0 + rl;
        int gi = rl >> 5, l = rl & 31;
        u32 word = acc[rr];
        if (w == (row >> 5)) word &= ~((2u << (row & 31)) - 1u);
        stage[gi * 1024 + lane * 32 + ((l ^ lane) & 31)] = word;
    }
    __syncthreads();

#pragma unroll
    for (int gi = 0; gi < 2; gi++) {
        int gr = gr0 + gi;
        if (gr >= GROUPS) continue;
        size_t obase = (size_t)b * PB + ((size_t)gr * NWP + w0) * 32;
#pragma unroll
        for (int rep = 0; rep < 4; rep++) {
            int j = rep * 256 + tid;
            int wl = j >> 5, l = j & 31;
            if (w0 + wl < gr) continue;
            g_mask[obase + (size_t)wl * 32 + l] = stage[gi * 1024 + wl * 32 + ((l ^ wl) & 31)];
        }
    }
}

// mask phase 1: corner (rows<5120 x words<160) — launched with grid (WB1, RB1, BB)
__global__ void k_mask() { mask_body(blockIdx.z, blockIdx.x * 32, blockIdx.y * 64); }

// mask phase 2: everything else; skipped entirely when the phase-0 sweep finished
__global__ void k_mask2() {
    int b = blockIdx.z;
    if (g_doneG[b]) return;
    if (blockIdx.x < WB1 && blockIdx.y < RB1) return;   // fully inside corner
    mask_body(b, blockIdx.x * 32, blockIdx.y * 64);
}

// ---------------- greedy sweep (R5 body + phase-0/1 state handoff) ----------------
__global__ void __launch_bounds__(384, 1) k_sweep(float* __restrict__ out, int phase) {
    const int b = blockIdx.x, tid = threadIdx.x;
    const int myw = tid;
    const size_t mb = (size_t)b * PB;
    __shared__ u32 s_diag[32];
    __shared__ int s_keep[POST];
    __shared__ u32 s_k32;
    __shared__ int s_tot;

    if (phase == 1 && g_doneG[b]) return;

    const int gStart = phase ? W1 : 0;
    const int gEnd   = phase ? NW : W1;
    const int lim    = phase ? NW : W1;

    u32 r = 0;
    if (phase == 1) {
        int T = g_totG[b];
        for (int i = tid; i < T; i += 384) s_keep[i] = g_keepG[b][i];
        if (tid == 0) s_tot = T;
        __syncthreads();
        if (myw < W1) {
            r = g_rsave[b][myw];
        } else if (myw < NW) {
            // recover removed-bits for columns >= W1 by ORing all kept rows
            for (int j = 0; j < T; j += 8) {
                u32 m[8];
#pragma unroll
                for (int q = 0; q < 8; q++) {
                    int idx = j + q; idx = idx < T ? idx : T - 1;
                    int row = s_keep[idx];
                    m[q] = g_mask[mb + ((size_t)(row >> 5) * NWP + myw) * 32 + (row & 31)];
                }
#pragma unroll
                for (int q = 0; q < 8; q++) r |= m[q];
            }
        }
    } else {
        if (tid == 0) s_tot = 0;
    }

    u32 cur[32], nxt[32];
    if (myw >= gStart && myw < lim) {
        const uint4* p = reinterpret_cast<const uint4*>(
            &g_mask[mb + ((size_t)gStart * NWP + myw) * 32]);
#pragma unroll
        for (int i = 0; i < 8; i++) {
            uint4 v = p[i];
            cur[4*i] = v.x; cur[4*i+1] = v.y; cur[4*i+2] = v.z; cur[4*i+3] = v.w;
        }
    }
    __syncthreads();

    for (int g = gStart; g < gEnd; g++) {
        if (myw > g && myw < lim && g + 1 < gEnd) {
            const uint4* p = reinterpret_cast<const uint4*>(
                &g_mask[mb + ((size_t)(g + 1) * NWP + myw) * 32]);
#pragma unroll
            for (int i = 0; i < 8; i++) {
                uint4 v = p[i];
                nxt[4*i] = v.x; nxt[4*i+1] = v.y; nxt[4*i+2] = v.z; nxt[4*i+3] = v.w;
            }
        }
        if (myw == g) {
#pragma unroll
            for (int l = 0; l < 32; l++) s_diag[l] = cur[l];
            u32 rem = r;
            int cnt = s_tot;
            u32 kept = 0u;
            u32 cand = ~rem;
            while (cand && cnt < POST) {
                int l = __ffs(cand) - 1;
                kept |= 1u << l;
                s_keep[cnt++] = g * 32 + l;
                rem |= s_diag[l];
                cand &= ~rem & ~((2u << l) - 1u);
            }
            s_k32 = kept;
            s_tot = cnt;
        }
        __syncthreads();
        if (s_tot >= POST) break;
        u32 k32 = s_k32;
        if (myw > g && myw < lim) {
            if (k32) {
#pragma unroll
                for (int l = 0; l < 32; l++) r |= ((k32 >> l) & 1u) ? cur[l] : 0u;
            }
#pragma unroll
            for (int l = 0; l < 32; l++) cur[l] = nxt[l];
        }
        __syncthreads();
    }

    __syncthreads();
    const int tot = s_tot;

    if (phase == 0) {
        g_rsave[b][myw] = r;
        for (int i = tid; i < tot; i += 384) g_keepG[b][i] = s_keep[i];
        if (tid == 0) { g_totG[b] = tot; g_doneG[b] = (tot >= POST) ? 1 : 0; }
        if (tot < POST) return;                 // phase 1 finishes & writes output
    }

    for (int i = tid; i < POST; i += blockDim.x) {
        float v0 = 0.f, v1 = 0.f, v2 = 0.f, v3 = 0.f, v4 = 0.f;
        if (i < tot) {
            int pos = s_keep[i];
            int gx = b * PP + pos;
            v0 = (float)b;
            v1 = g_sx1[gx]; v2 = g_sy1[gx]; v3 = g_sx2[gx]; v4 = g_sy2[gx];
        }
        float* o = out + (size_t)(b * POST + i) * 5;
        o[0] = v0; o[1] = v1; o[2] = v2; o[3] = v3; o[4] = v4;
    }
}

// ---------------- launcher ----------------
extern "C" void kernel_launch(void* const* d_in, const int* in_sizes, int n_in,
                              void* d_out, int out_size) {
    const float4* anchors = (const float4*)d_in[0];
    const float4* deltas  = (const float4*)d_in[1];
    const float*  scores  = (const float*)d_in[2];
    float* out = (float*)d_out;

    k_decode<<<(BB * NN + 255) / 256, 256>>>(anchors, deltas, scores);
    k_scan<<<BB, 1024>>>();
    k_scatter<<<(BB * NN + 255) / 256, 256>>>(scores);
    k_bsort<<<(BB * NBUCK + 255) / 256, 256>>>();
    k_gather<<<(BB * PP + 255) / 256, 256>>>();
    dim3 m1(WB1, RB1, BB);
    k_mask<<<m1, 256>>>();                     // corner only
    k_sweep<<<BB, 384>>>(out, 0);              // phase 0 (160 groups)
    dim3 m2(12, 188, BB);
    k_mask2<<<m2, 256>>>();                    // rest (skips when done)
    k_sweep<<<BB, 384>>>(out, 1);              // resume (skips when done)
}

// round 17
// speedup vs baseline: 4.5686x; 1.1495x over previous
#include <cuda_runtime.h>
#include <cstdint>
#include <math.h>

#define BB 8
#define NN 27380
#define PP 12000
#define POST 2000
#define NW 375            // PP/32 bit-words per row (logical)
#define NWP 384           // padded row stride in words
#define GROUPS 375
#define PB (GROUPS * NWP * 32)   // per-batch mask words (group-tiled layout)
#define NBUCK 8192
#define W1 128            // phase-0 column-word / group limit (rows/cols < 4096)
#define RB1 64            // row blocks (64 rows) covering rows < 4096
#define WB1 4             // col blocks (32 words) covering words < 128

typedef unsigned int u32;
typedef unsigned long long u64;

// ---------------- scratch (device globals; zero-initialized at load) ----------------
__device__ float4 g_boxes[BB * NN];
__device__ u32    g_cnt[BB * NBUCK];       // reset by k_scan each run
__device__ u32    g_start[BB * NBUCK];
__device__ u32    g_fill[BB * NBUCK];
__device__ u64    g_keys[BB * NN];
__device__ float  g_sx1[BB * PP], g_sy1[BB * PP], g_sx2[BB * PP], g_sy2[BB * PP], g_sa[BB * PP];
__device__ u32    g_mask[BB * PB];         // 147.5 MB
// sweep phase-0 -> phase-1 handoff state (deterministic data flow)
__device__ u32    g_rsave[BB][384];
__device__ int    g_keepG[BB][POST];
__device__ int    g_totG[BB];
__device__ int    g_doneG[BB];

// ---------------- kernel 1: decode boxes + bucket histogram ----------------
__global__ void k_decode(const float4* __restrict__ anchors,
                         const float4* __restrict__ deltas,
                         const float*  __restrict__ scores) {
    int i = blockIdx.x * blockDim.x + threadIdx.x;
    if (i < BB) g_doneG[i] = 0;            // reset per replay (runs before sweeps)
    if (i >= BB * NN) return;
    int n = i % NN;
    float4 a = anchors[n];
    float4 d = deltas[i];

    float w  = __fadd_rn(__fsub_rn(a.z, a.x), 1.0f);
    float h  = __fadd_rn(__fsub_rn(a.w, a.y), 1.0f);
    float cx = __fadd_rn(a.x, __fmul_rn(0.5f, w));
    float cy = __fadd_rn(a.y, __fmul_rn(0.5f, h));
    float px = __fadd_rn(cx, __fmul_rn(w, d.x));
    float py = __fadd_rn(cy, __fmul_rn(h, d.y));
    float pw = __fmul_rn((float)exp((double)d.z), w);
    float ph = __fmul_rn((float)exp((double)d.w), h);
    float x1 = __fsub_rn(px, __fmul_rn(0.5f, pw));
    float y1 = __fsub_rn(py, __fmul_rn(0.5f, ph));
    float x2 = __fadd_rn(px, __fmul_rn(0.5f, __fsub_rn(pw, 2.0f)));
    float y2 = __fadd_rn(py, __fmul_rn(0.5f, __fsub_rn(ph, 2.0f)));
    g_boxes[i] = make_float4(x1, y1, x2, y2);

    float s = scores[i];
    int t = (int)(s * 8192.0f);
    if (t > NBUCK - 1) t = NBUCK - 1;
    int bi = (NBUCK - 1) - t;
    atomicAdd(&g_cnt[(i / NN) * NBUCK + bi], 1u);
}

// ---------------- kernel 2: per-batch exclusive scan (+ counter reset) ----------------
__global__ void k_scan() {
    int b = blockIdx.x, tid = threadIdx.x;
    int lane = tid & 31, wid = tid >> 5;
    __shared__ u32 wsum[32];
    int base = b * NBUCK + tid * 8;
    u32 v[8], pre[8], s = 0;
#pragma unroll
    for (int j = 0; j < 8; j++) v[j] = g_cnt[base + j];
#pragma unroll
    for (int j = 0; j < 8; j++) { pre[j] = s; s += v[j]; }
#pragma unroll
    for (int j = 0; j < 8; j++) g_cnt[base + j] = 0u;
    u32 inc = s;
#pragma unroll
    for (int o = 1; o < 32; o <<= 1) { u32 t = __shfl_up_sync(~0u, inc, o); if (lane >= o) inc += t; }
    if (lane == 31) wsum[wid] = inc;
    __syncthreads();
    if (wid == 0) {
        u32 x = wsum[lane], xin = x;
#pragma unroll
        for (int o = 1; o < 32; o <<= 1) { u32 t = __shfl_up_sync(~0u, xin, o); if (lane >= o) xin += t; }
        wsum[lane] = xin - x;
    }
    __syncthreads();
    u32 off = wsum[wid] + (inc - s);
#pragma unroll
    for (int j = 0; j < 8; j++) {
        u32 o = off + pre[j];
        g_start[base + j] = o;
        g_fill[base + j]  = o;
    }
}

// ---------------- kernel 3: scatter keys into buckets ----------------
__global__ void k_scatter(const float* __restrict__ scores) {
    int i = blockIdx.x * blockDim.x + threadIdx.x;
    if (i >= BB * NN) return;
    int b = i / NN, n = i % NN;
    float s = scores[i];
    int t = (int)(s * 8192.0f);
    if (t > NBUCK - 1) t = NBUCK - 1;
    int bi = (NBUCK - 1) - t;
    u32 pos = atomicAdd(&g_fill[b * NBUCK + bi], 1u);
    u64 key = ((u64)__float_as_uint(s) << 32) | (u64)(0xFFFFFFFFu - (u32)n);
    g_keys[(size_t)b * NN + pos] = key;
}

// ---------------- kernel 4: per-bucket insertion sort (descending) ----------------
__global__ void k_bsort() {
    int i = blockIdx.x * blockDim.x + threadIdx.x;
    if (i >= BB * NBUCK) return;
    int b = i / NBUCK, bi = i % NBUCK;
    int s = (int)g_start[b * NBUCK + bi];
    if (s >= PP) return;                       // beyond top-P: never read
    int e = (bi == NBUCK - 1) ? NN : (int)g_start[b * NBUCK + bi + 1];
    u64* keys = &g_keys[(size_t)b * NN];
    for (int p = s + 1; p < e; p++) {
        u64 k = keys[p];
        int j = p - 1;
        while (j >= s && keys[j] < k) { keys[j + 1] = keys[j]; j--; }
        keys[j + 1] = k;
    }
}

// ---------------- kernel 5: gather top-P sorted boxes (SoA) + areas ----------------
__global__ void k_gather() {
    int i = blockIdx.x * blockDim.x + threadIdx.x;
    if (i >= BB * PP) return;
    int b = i / PP, p = i % PP;
    u64 k = g_keys[(size_t)b * NN + p];
    u32 n = 0xFFFFFFFFu - (u32)(k & 0xFFFFFFFFull);
    float4 bx = g_boxes[b * NN + n];
    g_sx1[i] = bx.x; g_sy1[i] = bx.y; g_sx2[i] = bx.z; g_sy2[i] = bx.w;
    g_sa[i] = __fmul_rn(__fadd_rn(__fsub_rn(bx.z, bx.x), 1.0f),
                        __fadd_rn(__fsub_rn(bx.w, bx.y), 1.0f));
}

// exact: rn(inter/denom) > 0.7f  <=>  inter*2^25 >= 23488103*denom
__device__ __forceinline__ bool iou_exact(float inter, float denom) {
    return ((double)inter * 33554432.0) >= (23488103.0 * (double)denom);
}

// screen thresholds: CC = 7/17 (iou>0.7 <=> inter > CC*(A+B)), band +-2e-6 relative
#define THI 0.41176671f
#define TLO 0.41176271f

// ---------------- mask body (R5 verbatim, parameterized) ----------------
__device__ __forceinline__ void mask_body(int b, int w0, int r0) {
    const int gr0 = r0 >> 5;
    if (w0 + 31 < gr0) return;                        // fully lower-triangle

    __shared__ float sx1[1024], sy1[1024], sx2p[1024], sy2p[1024], sa[1024];
    __shared__ u32 stage[2048];
    const int tid = threadIdx.x, lane = tid & 31, wi = tid >> 5;
    const int cbase = w0 * 32;
    for (int i = tid; i < 1024; i += 256) {
        int c = cbase + i;
        float x1 = 0.f, y1 = 0.f, x2 = -10.f, y2 = -10.f, a = 1.f;
        if (c < PP) {
            int g = b * PP + c;
            x1 = g_sx1[g]; y1 = g_sy1[g]; x2 = g_sx2[g]; y2 = g_sy2[g]; a = g_sa[g];
        }
        int sw = (i & 31) * 32 + (i >> 5);
        sx1[sw] = x1; sy1[sw] = y1;
        sx2p[sw] = __fadd_rn(x2, 1.0f);
        sy2p[sw] = __fadd_rn(y2, 1.0f);
        sa[sw] = a;
    }
    __syncthreads();

    const int w = w0 + lane;
    const int rbeg = r0 + wi * 8;
    float rx1[8], ry1[8], rx2p[8], ry2p[8], ra[8];
#pragma unroll
    for (int rr = 0; rr < 8; rr++) {
        int row = rbeg + rr;
        if (row < PP) {
            int g = b * PP + row;
            rx1[rr] = g_sx1[g]; ry1[rr] = g_sy1[g];
            rx2p[rr] = __fadd_rn(g_sx2[g], 1.0f);
            ry2p[rr] = __fadd_rn(g_sy2[g], 1.0f);
            ra[rr] = g_sa[g];
        } else { rx1[rr] = 0.f; ry1[rr] = 0.f; rx2p[rr] = -9.f; ry2p[rr] = -9.f; ra[rr] = 1.f; }
    }
    u32 acc[8] = {0,0,0,0,0,0,0,0};
    u32 rar[8] = {0,0,0,0,0,0,0,0};

#pragma unroll 4
    for (int t = 0; t < 32; t++) {
        int si = t * 32 + lane;
        float cx1 = sx1[si], cy1 = sy1[si], cx2p = sx2p[si], cy2p = sy2p[si], ca = sa[si];
#pragma unroll
        for (int rr = 0; rr < 8; rr++) {
            float xx1 = fmaxf(rx1[rr], cx1);
            float yy1 = fmaxf(ry1[rr], cy1);
            float ww  = __fsub_rn(fminf(rx2p[rr], cx2p), xx1);
            float hh  = fmaxf(__fsub_rn(fminf(ry2p[rr], cy2p), yy1), 0.0f);
            float inter = __fmul_rn(ww, hh);
            float s     = __fadd_rn(ra[rr], ca);
            acc[rr] |= (__fmaf_rn(-THI, s, inter) > 0.0f) ? (1u << t) : 0u;
            rar[rr] |= (__fmaf_rn(-TLO, s, inter) > 0.0f) ? (1u << t) : 0u;
        }
    }
#pragma unroll
    for (int rr = 0; rr < 8; rr++) rar[rr] &= ~acc[rr];

    u32 any = rar[0]|rar[1]|rar[2]|rar[3]|rar[4]|rar[5]|rar[6]|rar[7];
    if (any) {
#pragma unroll
        for (int rr = 0; rr < 8; rr++) {
            u32 m = rar[rr];
            while (m) {
                int t = __ffs(m) - 1; m &= m - 1;
                int si = t * 32 + lane;
                float cx1 = sx1[si], cy1 = sy1[si], cx2p = sx2p[si], cy2p = sy2p[si], ca = sa[si];
                float xx1 = fmaxf(rx1[rr], cx1);
                float yy1 = fmaxf(ry1[rr], cy1);
                float ww  = fmaxf(__fsub_rn(fminf(rx2p[rr], cx2p), xx1), 0.0f);
                float hh  = fmaxf(__fsub_rn(fminf(ry2p[rr], cy2p), yy1), 0.0f);
                float inter = __fmul_rn(ww, hh);
                float denom = __fsub_rn(__fadd_rn(ra[rr], ca), inter);
                if (iou_exact(inter, denom)) acc[rr] |= (1u << t);
            }
        }
    }

#pragma unroll
    for (int rr = 0; rr < 8; rr++) {
        int rl = wi * 8 + rr;
        int row = r0 + rl;
        int gi = rl >> 5, l = rl & 31;
        u32 word = acc[rr];
        if (w == (row >> 5)) word &= ~((2u << (row & 31)) - 1u);
        stage[gi * 1024 + lane * 32 + ((l ^ lane) & 31)] = word;
    }
    __syncthreads();

#pragma unroll
    for (int gi = 0; gi < 2; gi++) {
        int gr = gr0 + gi;
        if (gr >= GROUPS) continue;
        size_t obase = (size_t)b * PB + ((size_t)gr * NWP + w0) * 32;
#pragma unroll
        for (int rep = 0; rep < 4; rep++) {
            int j = rep * 256 + tid;
            int wl = j >> 5, l = j & 31;
            if (w0 + wl < gr) continue;
            g_mask[obase + (size_t)wl * 32 + l] = stage[gi * 1024 + wl * 32 + ((l ^ wl) & 31)];
        }
    }
}

// mask phase 1: corner (rows<4096 x words<128) — launched with grid (WB1, RB1, BB)
__global__ void k_mask() { mask_body(blockIdx.z, blockIdx.x * 32, blockIdx.y * 64); }

// mask phase 2: everything else; skipped entirely when the phase-0 sweep finished
__global__ void k_mask2() {
    int b = blockIdx.z;
    if (g_doneG[b]) return;
    if (blockIdx.x < WB1 && blockIdx.y < RB1) return;   // fully inside corner
    mask_body(b, blockIdx.x * 32, blockIdx.y * 64);
}

// ---------------- greedy sweep (R5 body + phase-0/1 state handoff) ----------------
__global__ void __launch_bounds__(384, 1) k_sweep(float* __restrict__ out, int phase) {
    const int b = blockIdx.x, tid = threadIdx.x;
    const int myw = tid;
    const size_t mb = (size_t)b * PB;
    __shared__ u32 s_diag[32];
    __shared__ int s_keep[POST];
    __shared__ u32 s_k32;
    __shared__ int s_tot;

    if (phase == 1 && g_doneG[b]) return;

    const int gStart = phase ? W1 : 0;
    const int gEnd   = phase ? NW : W1;
    const int lim    = phase ? NW : W1;

    u32 r = 0;
    if (phase == 1) {
        int T = g_totG[b];
        for (int i = tid; i < T; i += 384) s_keep[i] = g_keepG[b][i];
        if (tid == 0) s_tot = T;
        __syncthreads();
        if (myw < W1) {
            r = g_rsave[b][myw];
        } else if (myw < NW) {
            // recover removed-bits for columns >= W1 by ORing all kept rows
            for (int j = 0; j < T; j += 8) {
                u32 m[8];
#pragma unroll
                for (int q = 0; q < 8; q++) {
                    int idx = j + q; idx = idx < T ? idx : T - 1;
                    int row = s_keep[idx];
                    m[q] = g_mask[mb + ((size_t)(row >> 5) * NWP + myw) * 32 + (row & 31)];
                }
#pragma unroll
                for (int q = 0; q < 8; q++) r |= m[q];
            }
        }
    } else {
        if (tid == 0) s_tot = 0;
    }

    u32 cur[32], nxt[32];
    if (myw >= gStart && myw < lim) {
        const uint4* p = reinterpret_cast<const uint4*>(
            &g_mask[mb + ((size_t)gStart * NWP + myw) * 32]);
#pragma unroll
        for (int i = 0; i < 8; i++) {
            uint4 v = p[i];
            cur[4*i] = v.x; cur[4*i+1] = v.y; cur[4*i+2] = v.z; cur[4*i+3] = v.w;
        }
    }
    __syncthreads();

    for (int g = gStart; g < gEnd; g++) {
        if (myw > g && myw < lim && g + 1 < gEnd) {
            const uint4* p = reinterpret_cast<const uint4*>(
                &g_mask[mb + ((size_t)(g + 1) * NWP + myw) * 32]);
#pragma unroll
            for (int i = 0; i < 8; i++) {
                uint4 v = p[i];
                nxt[4*i] = v.x; nxt[4*i+1] = v.y; nxt[4*i+2] = v.z; nxt[4*i+3] = v.w;
            }
        }
        if (myw == g) {
#pragma unroll
            for (int l = 0; l < 32; l++) s_diag[l] = cur[l];
            u32 rem = r;
            int cnt = s_tot;
            u32 kept = 0u;
            u32 cand = ~rem;
            while (cand && cnt < POST) {
                int l = __ffs(cand) - 1;
                kept |= 1u << l;
                s_keep[cnt++] = g * 32 + l;
                rem |= s_diag[l];
                cand &= ~rem & ~((2u << l) - 1u);
            }
            s_k32 = kept;
            s_tot = cnt;
        }
        __syncthreads();
        if (s_tot >= POST) break;
        u32 k32 = s_k32;
        if (myw > g && myw < lim) {
            if (k32) {
#pragma unroll
                for (int l = 0; l < 32; l++) r |= ((k32 >> l) & 1u) ? cur[l] : 0u;
            }
#pragma unroll
            for (int l = 0; l < 32; l++) cur[l] = nxt[l];
        }
        __syncthreads();
    }

    __syncthreads();
    const int tot = s_tot;

    if (phase == 0) {
        g_rsave[b][myw] = r;
        for (int i = tid; i < tot; i += 384) g_keepG[b][i] = s_keep[i];
        if (tid == 0) { g_totG[b] = tot; g_doneG[b] = (tot >= POST) ? 1 : 0; }
        if (tot < POST) return;                 // phase 1 finishes & writes output
    }

    for (int i = tid; i < POST; i += blockDim.x) {
        float v0 = 0.f, v1 = 0.f, v2 = 0.f, v3 = 0.f, v4 = 0.f;
        if (i < tot) {
            int pos = s_keep[i];
            int gx = b * PP + pos;
            v0 = (float)b;
            v1 = g_sx1[gx]; v2 = g_sy1[gx]; v3 = g_sx2[gx]; v4 = g_sy2[gx];
        }
        float* o = out + (size_t)(b * POST + i) * 5;
        o[0] = v0; o[1] = v1; o[2] = v2; o[3] = v3; o[4] = v4;
    }
}

// ---------------- launcher ----------------
extern "C" void kernel_launch(void* const* d_in, const int* in_sizes, int n_in,
                              void* d_out, int out_size) {
    const float4* anchors = (const float4*)d_in[0];
    const float4* deltas  = (const float4*)d_in[1];
    const float*  scores  = (const float*)d_in[2];
    float* out = (float*)d_out;

    k_decode<<<(BB * NN + 255) / 256, 256>>>(anchors, deltas, scores);
    k_scan<<<BB, 1024>>>();
    k_scatter<<<(BB * NN + 255) / 256, 256>>>(scores);
    k_bsort<<<(BB * NBUCK + 255) / 256, 256>>>();
    k_gather<<<(BB * PP + 255) / 256, 256>>>();
    dim3 m1(WB1, RB1, BB);
    k_mask<<<m1, 256>>>();                     // corner only
    k_sweep<<<BB, 384>>>(out, 0);              // phase 0 (128 groups)
    dim3 m2(12, 188, BB);
    k_mask2<<<m2, 256>>>();                    // rest (skips when done)
    k_sweep<<<BB, 384>>>(out, 1);              // resume (skips when done)
}